// round 2
// baseline (speedup 1.0000x reference)
#include <cuda_runtime.h>
#include <math.h>

// StatEncoder: bidirectional-GRU-ish encoder.
//   forward GRU over W=128 steps (only final h used)
//   backward GRU = single cell at h0=0 on x[:, -1, :]
//   head: GELU(concat @ Wp^T + bp) -> LayerNorm
//
// Round-1 baseline: fp32 SIMT, one launch per timestep (launch boundary
// provides the h(t) -> h(t+1) synchronization). Gate-transposed fused
// weight matrix Wt[k][gate*256+j] (k<256: Whh, k>=256: Wih) gives coalesced
// weight loads and folds the input projection into the same K loop.

#define Bsz  2048
#define Wlen 128
#define Fin  8
#define Hdim 256
#define G3   768          // 3*H
#define Kx   264          // 256 (h) + 8 (x)

// ---- scratch (static __device__: no runtime allocation) ----
__device__ float g_Wt[Kx * G3];            // [k][col], col = gate*256 + j   (~811 KB)
__device__ float g_Wpt[(2 * Hdim) * Hdim]; // transposed Wp: [m][j]          (512 KB)
__device__ float g_h[2][Bsz * Hdim];       // double-buffered hidden state   (4 MB)

// ---------------------------------------------------------------------------
// prep: build Wt, Wpt, zero h0. Idempotent; runs every launch (determinism).
// ---------------------------------------------------------------------------
__global__ void prep_kernel(const float* __restrict__ Whh_f,
                            const float* __restrict__ Wih_f,
                            const float* __restrict__ Wp) {
    int idx = blockIdx.x * blockDim.x + threadIdx.x;
    const int N1 = Kx * G3;            // 202752
    const int N2 = 2 * Hdim * Hdim;    // 131072
    const int N3 = Bsz * Hdim;         // 524288
    if (idx < N1) {
        int k = idx / G3, col = idx - k * G3;
        g_Wt[idx] = (k < Hdim) ? Whh_f[col * Hdim + k]
                               : Wih_f[col * Fin + (k - Hdim)];
    } else if (idx < N1 + N2) {
        int i = idx - N1;
        int m = i / Hdim, j = i - m * Hdim;
        g_Wpt[i] = Wp[j * (2 * Hdim) + m];
    } else if (idx < N1 + N2 + N3) {
        g_h[0][idx - N1 - N2] = 0.0f;
    }
}

// ---------------------------------------------------------------------------
// One GRU step. Grid (2, 64): blockIdx.x = j-tile (128 h-cols),
// blockIdx.y = batch tile (32 rows). 256 threads.
// Each thread: one j column, 16 batch rows, 4 accumulators per row.
// ---------------------------------------------------------------------------
__global__ __launch_bounds__(256, 2)
void gru_step_kernel(const float* __restrict__ x,
                     const float* __restrict__ bih,
                     const float* __restrict__ bhh,
                     int t, int inbuf) {
    __shared__ float hs[32][Kx];   // 32 rows x (256 h-cols + 8 x-cols)

    const int tx    = threadIdx.x;
    const int b0    = blockIdx.y * 32;
    const int j0    = blockIdx.x * 128 + (tx & 127);  // h column, 0..255
    const int rbase = (tx >> 7) * 16;                 // constant per warp

    const float* __restrict__ hin  = g_h[inbuf];
    float* __restrict__       hout = g_h[inbuf ^ 1];

    // load h tile (coalesced)
    for (int idx = tx; idx < 32 * Hdim; idx += 256) {
        int r = idx >> 8, k = idx & 255;
        hs[r][k] = hin[(b0 + r) * Hdim + k];
    }
    // load x(t) tile into the K-extension columns
    for (int idx = tx; idx < 32 * Fin; idx += 256) {
        int r = idx >> 3, c = idx & 7;
        hs[r][Hdim + c] = x[(b0 + r) * (Wlen * Fin) + t * Fin + c];
    }
    __syncthreads();

    float accr[16], accz[16], acchn[16], accinn[16];
#pragma unroll
    for (int i = 0; i < 16; i++) { accr[i] = 0.f; accz[i] = 0.f; acchn[i] = 0.f; accinn[i] = 0.f; }

    const float* __restrict__ WtR = g_Wt + j0;
    const float* __restrict__ WtZ = g_Wt + 256 + j0;
    const float* __restrict__ WtN = g_Wt + 512 + j0;

    // hidden part: k < 256 (n-gate contribution goes to acchn)
#pragma unroll 2
    for (int k = 0; k < Hdim; k++) {
        float wr = WtR[k * G3], wz = WtZ[k * G3], wn = WtN[k * G3];
#pragma unroll
        for (int i = 0; i < 16; i++) {
            float hv = hs[rbase + i][k];                 // warp broadcast
            accr[i]  = fmaf(hv, wr, accr[i]);
            accz[i]  = fmaf(hv, wz, accz[i]);
            acchn[i] = fmaf(hv, wn, acchn[i]);
        }
    }
    // input part: k in [256, 264) (n-gate contribution goes to accinn)
#pragma unroll
    for (int k = Hdim; k < Kx; k++) {
        float wr = WtR[k * G3], wz = WtZ[k * G3], wn = WtN[k * G3];
#pragma unroll
        for (int i = 0; i < 16; i++) {
            float hv = hs[rbase + i][k];
            accr[i]   = fmaf(hv, wr, accr[i]);
            accz[i]   = fmaf(hv, wz, accz[i]);
            accinn[i] = fmaf(hv, wn, accinn[i]);
        }
    }

    const float bir = bih[j0],       bhr = bhh[j0];
    const float biz = bih[256 + j0], bhz = bhh[256 + j0];
    const float bin = bih[512 + j0], bhn = bhh[512 + j0];

#pragma unroll
    for (int i = 0; i < 16; i++) {
        int   row = rbase + i;
        float ar = accr[i] + bir + bhr;
        float az = accz[i] + biz + bhz;
        float r  = 1.0f / (1.0f + __expf(-ar));
        float z  = 1.0f / (1.0f + __expf(-az));
        float an = (accinn[i] + bin) + r * (acchn[i] + bhn);
        an = fminf(fmaxf(an, -15.0f), 15.0f);   // tanh saturates; avoids inf/inf
        float e  = __expf(-2.0f * an);
        float n  = (1.0f - e) / (1.0f + e);
        float ho = hs[row][j0];
        hout[(b0 + row) * Hdim + j0] = (1.0f - z) * n + z * ho;
    }
}

// ---------------------------------------------------------------------------
// Head: h_bwd (closed form, h0=0) + projection + exact GELU + LayerNorm.
// One block per 8 batch rows, 256 threads.
// ---------------------------------------------------------------------------
__global__ __launch_bounds__(256)
void head_kernel(const float* __restrict__ x,
                 const float* __restrict__ Wih_b,
                 const float* __restrict__ bih_b,
                 const float* __restrict__ bhh_b,
                 const float* __restrict__ bp,
                 const float* __restrict__ gamma,
                 const float* __restrict__ beta,
                 float* __restrict__ out) {
    __shared__ float hf[8][Hdim];
    __shared__ float hb[8][Hdim];
    __shared__ float ys[8][Hdim];
    __shared__ float xs[8][Fin];

    const int tx = threadIdx.x;
    const int b0 = blockIdx.x * 8;
    const float* __restrict__ h0 = g_h[0];   // after 128 steps, final h is in buffer 0

    for (int idx = tx; idx < 8 * Hdim; idx += 256) {
        int r = idx >> 8, k = idx & 255;
        hf[r][k] = h0[(b0 + r) * Hdim + k];
    }
    if (tx < 64) {
        int r = tx >> 3, c = tx & 7;
        xs[r][c] = x[(b0 + r) * (Wlen * Fin) + (Wlen - 1) * Fin + c];
    }
    __syncthreads();

    // backward cell at h=0: gh = bhh_b, so h_bwd = (1-z)*n with
    // r = sig(gi_r + bhh_r), z = sig(gi_z + bhh_z), n = tanh(gi_n + r*bhh_n)
    {
        const int j = tx;
        float wr[Fin], wz[Fin], wn[Fin];
#pragma unroll
        for (int c = 0; c < Fin; c++) {
            wr[c] = Wih_b[j * Fin + c];
            wz[c] = Wih_b[(256 + j) * Fin + c];
            wn[c] = Wih_b[(512 + j) * Fin + c];
        }
        const float bir = bih_b[j],       bhr = bhh_b[j];
        const float biz = bih_b[256 + j], bhz = bhh_b[256 + j];
        const float bin = bih_b[512 + j], bhn = bhh_b[512 + j];
#pragma unroll
        for (int r8 = 0; r8 < 8; r8++) {
            float gr = bir + bhr, gz = biz + bhz, gn = bin;
#pragma unroll
            for (int c = 0; c < Fin; c++) {
                float xv = xs[r8][c];
                gr = fmaf(xv, wr[c], gr);
                gz = fmaf(xv, wz[c], gz);
                gn = fmaf(xv, wn[c], gn);
            }
            float r  = 1.0f / (1.0f + __expf(-gr));
            float z  = 1.0f / (1.0f + __expf(-gz));
            float an = gn + r * bhn;
            an = fminf(fmaxf(an, -15.0f), 15.0f);
            float e  = __expf(-2.0f * an);
            float n  = (1.0f - e) / (1.0f + e);
            hb[r8][j] = (1.0f - z) * n;
        }
    }
    __syncthreads();

    // y = GELU_exact( [hf|hb] @ Wp^T + bp )
    {
        const int j = tx;
#pragma unroll
        for (int r8 = 0; r8 < 8; r8++) {
            float acc = bp[j];
#pragma unroll 4
            for (int k = 0; k < Hdim; k++)
                acc = fmaf(hf[r8][k], g_Wpt[k * Hdim + j], acc);
#pragma unroll 4
            for (int k = 0; k < Hdim; k++)
                acc = fmaf(hb[r8][k], g_Wpt[(Hdim + k) * Hdim + j], acc);
            ys[r8][j] = 0.5f * acc * (1.0f + erff(acc * 0.70710678118654752f));
        }
    }
    __syncthreads();

    // LayerNorm: warp w handles row w
    const int w = tx >> 5, l = tx & 31;
    float s1 = 0.f, s2 = 0.f;
#pragma unroll
    for (int m = 0; m < 8; m++) {
        float v = ys[w][l + 32 * m];
        s1 += v; s2 += v * v;
    }
#pragma unroll
    for (int o = 16; o > 0; o >>= 1) {
        s1 += __shfl_xor_sync(0xffffffffu, s1, o);
        s2 += __shfl_xor_sync(0xffffffffu, s2, o);
    }
    const float mu  = s1 * (1.0f / 256.0f);
    const float var = s2 * (1.0f / 256.0f) - mu * mu;
    const float inv = rsqrtf(var + 1e-5f);
#pragma unroll
    for (int m = 0; m < 8; m++) {
        int col = l + 32 * m;
        float v = (ys[w][col] - mu) * inv;
        out[(b0 + w) * Hdim + col] = v * gamma[col] + beta[col];
    }
}

// ---------------------------------------------------------------------------
extern "C" void kernel_launch(void* const* d_in, const int* in_sizes, int n_in,
                              void* d_out, int out_size) {
    const float* x     = (const float*)d_in[0];
    const float* Wih_f = (const float*)d_in[1];
    const float* Whh_f = (const float*)d_in[2];
    const float* bih_f = (const float*)d_in[3];
    const float* bhh_f = (const float*)d_in[4];
    const float* Wih_b = (const float*)d_in[5];
    /* Whh_b = d_in[6] is mathematically unused (h0 = 0 backward cell) */
    const float* bih_b = (const float*)d_in[7];
    const float* bhh_b = (const float*)d_in[8];
    const float* Wp    = (const float*)d_in[9];
    const float* bp    = (const float*)d_in[10];
    const float* gamma = (const float*)d_in[11];
    const float* beta  = (const float*)d_in[12];
    float* out = (float*)d_out;

    const int totalPrep = Kx * G3 + 2 * Hdim * Hdim + Bsz * Hdim;
    prep_kernel<<<(totalPrep + 255) / 256, 256>>>(Whh_f, Wih_f, Wp);

    for (int t = 0; t < Wlen; t++) {
        gru_step_kernel<<<dim3(2, 64), 256>>>(x, bih_f, bhh_f, t, t & 1);
    }

    head_kernel<<<Bsz / 8, 256>>>(x, Wih_b, bih_b, bhh_b, bp, gamma, beta, out);
}